// round 14
// baseline (speedup 1.0000x reference)
#include <cuda_runtime.h>
#include <cuda_bf16.h>
#include <cstdint>

#define BATCH  16384
#define DIM    128
#define NREL   500
#define MAXC   2048
#define SUBCAP 256
#define ALPHA  0.001f
#define KPB    272       // bytes per bf16 tile row (136 elems -> conflict-free LDS.32)

// device scratch (zero-init at load; self-cleaning across graph replays)
__device__ float g_accs[32][4];  // spread accumulators: [slot][h2,t2,r2c,sq]
__device__ int   g_cnt8[NREL * 8];
__device__ int   g_bucket[NREL * MAXC];
__device__ int   g_ready;
__device__ int   g_done;

#define OFF_RLO    (128 * KPB)          // 34816
#define SMEM_TOTAL (2 * 128 * KPB)      // 69632 -> 3 CTAs/SM

extern __shared__ char smem[];

__device__ __forceinline__ float warpSum(float v) {
#pragma unroll
    for (int o = 16; o > 0; o >>= 1) v += __shfl_xor_sync(0xffffffffu, v, o);
    return v;
}

__device__ __forceinline__ void split_u32(float x, float y, uint32_t& hi, uint32_t& lo) {
    __nv_bfloat162 h = __floats2bfloat162_rn(x, y);
    __nv_bfloat162 l = __floats2bfloat162_rn(x - __bfloat162float(h.x),
                                             y - __bfloat162float(h.y));
    hi = *reinterpret_cast<uint32_t*>(&h);
    lo = *reinterpret_cast<uint32_t*>(&l);
}

__device__ __forceinline__ void mma_bf16(float& c0, float& c1, float& c2, float& c3,
                                         uint32_t a0, uint32_t a1, uint32_t a2, uint32_t a3,
                                         uint32_t b0, uint32_t b1) {
    asm volatile(
        "mma.sync.aligned.m16n8k16.row.col.f32.bf16.bf16.f32 "
        "{%0,%1,%2,%3}, {%4,%5,%6,%7}, {%8,%9}, {%0,%1,%2,%3};"
        : "+f"(c0), "+f"(c1), "+f"(c2), "+f"(c3)
        : "r"(a0), "r"(a1), "r"(a2), "r"(a3), "r"(b0), "r"(b1));
}

// map logical row r -> global bucket index, via 8-segment prefix in smem
__device__ __forceinline__ int row_lookup(int r, const int* sP, int rel) {
    int sub = 0;
#pragma unroll
    for (int j = 1; j < 8; j++) sub += (r >= sP[j]);
    return g_bucket[rel * MAXC + sub * SUBCAP + (r - sP[sub])];
}

__global__ __launch_bounds__(128, 3) void rescal_fused(
    const int*   __restrict__ h_idx,
    const int*   __restrict__ r_idx,
    const int*   __restrict__ t_idx,
    const float* __restrict__ labels,
    const float* __restrict__ ent_w,
    const float* __restrict__ rel_w,
    float*       __restrict__ out)
{
    __shared__ float sH2, sT2, sE2, sR2;
    __shared__ int   sLast;
    __shared__ int   sP[9];

    const int tid  = threadIdx.x;
    const int lane = tid & 31;
    const int wid  = tid >> 5;
    const int rel  = blockIdx.x;

    char* Rhi = smem;
    char* Rlo = smem + OFF_RLO;

    if (tid == 0) { sH2 = 0.f; sT2 = 0.f; sE2 = 0.f; sR2 = 0.f; sLast = 0; }
    __syncthreads();

    // ---- Phase A: blocks 0..127 bucket 128 indices each; 8 sub-buckets/rel ----
    if (rel < 128) {
        int i   = rel * 128 + tid;
        int rl  = r_idx[i];
        int sub = i & 7;
        int s   = atomicAdd(&g_cnt8[rl * 8 + sub], 1);
        if (s < SUBCAP) g_bucket[rl * MAXC + sub * SUBCAP + s] = i;
        __threadfence();
        __syncthreads();
        if (tid == 0) atomicAdd(&g_ready, 1);
    }

    // ---- Phase B: R -> bf16 hi/lo smem tiles; 8-deep load batching (MLP 8) ----
    const float4* Rg = (const float4*)rel_w + (size_t)rel * 4096;
    float r2 = 0.f;
#pragma unroll
    for (int g = 0; g < 4; g++) {
        float4 v[8];
#pragma unroll
        for (int j = 0; j < 8; j++)
            v[j] = Rg[g * 1024 + j * 128 + tid];
#pragma unroll
        for (int j = 0; j < 8; j++) {
            int i   = g * 1024 + j * 128 + tid;
            int row = i >> 5;
            int col = (i & 31) * 4;
            r2 += v[j].x * v[j].x + v[j].y * v[j].y + v[j].z * v[j].z + v[j].w * v[j].w;
            uint32_t h0, l0, h1, l1;
            split_u32(v[j].x, v[j].y, h0, l0);
            split_u32(v[j].z, v[j].w, h1, l1);
            *(uint2*)(Rhi + row * KPB + col * 2) = make_uint2(h0, h1);
            *(uint2*)(Rlo + row * KPB + col * 2) = make_uint2(l0, l1);
        }
    }
    r2 = warpSum(r2);
    if (lane == 0) atomicAdd(&sR2, r2);

    // ---- Phase C: wait for bucket producers, then build segment prefix ----
    if (tid == 0) {
        volatile int* p = &g_ready;
        while (*p < 128) { }
        __threadfence();
    }
    __syncthreads();
    if (tid == 0) {
        int acc = 0;
        sP[0] = 0;
#pragma unroll
        for (int j = 0; j < 8; j++) {
            int c = g_cnt8[rel * 8 + j];
            acc += (c < SUBCAP ? c : SUBCAP);
            sP[j + 1] = acc;
        }
    }
    __syncthreads();
    const int count = sP[8];

    float h2 = 0.f, t2 = 0.f, sq = 0.f;
    const int gr  = lane >> 2;   // 0..7
    const int tig = lane & 3;    // 0..3

    // ---- Phase D: per-warp 16-row chunks; kt-outer / nt-inner MMA ----
    for (int base = wid * 16; base < count; base += 4 * 16) {
        const int ne   = min(16, count - base);
        const bool ok0 = (gr < ne);
        const bool ok1 = (gr + 8 < ne);

        const int ib0 = ok0 ? row_lookup(base + gr, sP, rel) : 0;
        const int ib1 = ok1 ? row_lookup(base + gr + 8, sP, rel) : 0;
        const float* T0 = ent_w + (size_t)t_idx[ib0] * DIM;
        const float* T1 = ent_w + (size_t)t_idx[ib1] * DIM;
        const float* H0 = ent_w + (size_t)h_idx[ib0] * DIM;
        const float* H1 = ent_w + (size_t)h_idx[ib1] * DIM;

        // preload all A-fragments (T rows gr / gr+8), split to bf16 hi/lo
        uint32_t ah[8][4], al[8][4];
#pragma unroll
        for (int kt = 0; kt < 8; kt++) {
            const int ka = kt * 16 + 2 * tig;
            float2 t0a = ok0 ? *(const float2*)(T0 + ka)     : make_float2(0.f, 0.f);
            float2 t0b = ok0 ? *(const float2*)(T0 + ka + 8) : make_float2(0.f, 0.f);
            float2 t1a = ok1 ? *(const float2*)(T1 + ka)     : make_float2(0.f, 0.f);
            float2 t1b = ok1 ? *(const float2*)(T1 + ka + 8) : make_float2(0.f, 0.f);
            t2 += t0a.x * t0a.x + t0a.y * t0a.y + t0b.x * t0b.x + t0b.y * t0b.y
                + t1a.x * t1a.x + t1a.y * t1a.y + t1b.x * t1b.x + t1b.y * t1b.y;
            split_u32(t0a.x, t0a.y, ah[kt][0], al[kt][0]);
            split_u32(t1a.x, t1a.y, ah[kt][1], al[kt][1]);
            split_u32(t0b.x, t0b.y, ah[kt][2], al[kt][2]);
            split_u32(t1b.x, t1b.y, ah[kt][3], al[kt][3]);
        }

        float s0 = 0.f, s1 = 0.f;

        // two halves of the n-dimension: 8 live accumulator groups each
#pragma unroll
        for (int hh = 0; hh < 2; hh++) {
            float acc[32];
#pragma unroll
            for (int j = 0; j < 32; j++) acc[j] = 0.f;

#pragma unroll
            for (int kt = 0; kt < 8; kt++) {
                const int kb = kt * 32 + 4 * tig;
#pragma unroll
                for (int nt = 0; nt < 8; nt++) {
                    const int n = (hh * 8 + nt) * 8 + gr;
                    const char* rh = Rhi + n * KPB;
                    const char* rl = Rlo + n * KPB;
                    uint32_t bh0 = *(const uint32_t*)(rh + kb);
                    uint32_t bh1 = *(const uint32_t*)(rh + kb + 16);
                    uint32_t bl0 = *(const uint32_t*)(rl + kb);
                    uint32_t bl1 = *(const uint32_t*)(rl + kb + 16);
                    float* c = acc + nt * 4;
                    mma_bf16(c[0], c[1], c[2], c[3],
                             ah[kt][0], ah[kt][1], ah[kt][2], ah[kt][3], bh0, bh1);
                    mma_bf16(c[0], c[1], c[2], c[3],
                             ah[kt][0], ah[kt][1], ah[kt][2], ah[kt][3], bl0, bl1);
                    mma_bf16(c[0], c[1], c[2], c[3],
                             al[kt][0], al[kt][1], al[kt][2], al[kt][3], bh0, bh1);
                }
            }

            // epilogue for this half: score += H . Y
#pragma unroll
            for (int nt = 0; nt < 8; nt++) {
                const int cn = (hh * 8 + nt) * 8 + 2 * tig;
                float2 hA = ok0 ? *(const float2*)(H0 + cn) : make_float2(0.f, 0.f);
                float2 hB = ok1 ? *(const float2*)(H1 + cn) : make_float2(0.f, 0.f);
                h2 += hA.x * hA.x + hA.y * hA.y + hB.x * hB.x + hB.y * hB.y;
                s0 += hA.x * acc[nt * 4 + 0] + hA.y * acc[nt * 4 + 1];
                s1 += hB.x * acc[nt * 4 + 2] + hB.y * acc[nt * 4 + 3];
            }
        }

        s0 += __shfl_xor_sync(0xffffffffu, s0, 1);
        s0 += __shfl_xor_sync(0xffffffffu, s0, 2);
        s1 += __shfl_xor_sync(0xffffffffu, s1, 1);
        s1 += __shfl_xor_sync(0xffffffffu, s1, 2);
        if (tig == 0) {
            if (ok0) {
                out[1 + ib0] = s0;
                float d = s0 - labels[ib0];
                sq += d * d;
            }
            if (ok1) {
                out[1 + ib1] = s1;
                float d = s1 - labels[ib1];
                sq += d * d;
            }
        }
    }

    // ---- Phase E: loss partials -> 32-way spread slots; last block finalizes ----
    h2 = warpSum(h2);
    t2 = warpSum(t2);
    sq = warpSum(sq);
    if (lane == 0) {
        atomicAdd(&sH2, h2);
        atomicAdd(&sT2, t2);
        atomicAdd(&sE2, sq);
    }
    __syncthreads();
    if (tid == 0) {
        const int slot = rel & 31;
        atomicAdd(&g_accs[slot][0], sH2);
        atomicAdd(&g_accs[slot][1], sT2);
        atomicAdd(&g_accs[slot][2], sR2 * (float)count);
        atomicAdd(&g_accs[slot][3], sE2);
        __threadfence();
        int old = atomicAdd(&g_done, 1);
        if (old == NREL - 1) sLast = 1;
    }
    __syncthreads();

    if (sLast) {
        for (int i = tid; i < NREL * 8; i += 128) g_cnt8[i] = 0;
        if (tid == 0) {
            __threadfence();
            float a0 = 0.f, a1 = 0.f, a2 = 0.f, a3 = 0.f;
#pragma unroll
            for (int s = 0; s < 32; s++) {
                a0 += __ldcg(&g_accs[s][0]);
                a1 += __ldcg(&g_accs[s][1]);
                a2 += __ldcg(&g_accs[s][2]);
                a3 += __ldcg(&g_accs[s][3]);
                g_accs[s][0] = 0.f; g_accs[s][1] = 0.f;
                g_accs[s][2] = 0.f; g_accs[s][3] = 0.f;
            }
            const float invBD  = 1.0f / ((float)BATCH * (float)DIM);
            const float invBDD = 1.0f / ((float)BATCH * (float)DIM * (float)DIM);
            float norms = (a0 * invBD + a1 * invBD + a2 * invBDD) * (1.0f / 3.0f);
            out[0] = a3 / (float)BATCH + ALPHA * norms;
            g_done  = 0;
            g_ready = 0;
        }
    }
}

extern "C" void kernel_launch(void* const* d_in, const int* in_sizes, int n_in,
                              void* d_out, int out_size)
{
    const int*   h_idx  = (const int*)d_in[0];
    const int*   r_idx  = (const int*)d_in[1];
    const int*   t_idx  = (const int*)d_in[2];
    const float* labels = (const float*)d_in[3];
    const float* ent_w  = (const float*)d_in[4];
    const float* rel_w  = (const float*)d_in[5];
    float*       out    = (float*)d_out;

    cudaFuncSetAttribute(rescal_fused,
                         cudaFuncAttributeMaxDynamicSharedMemorySize, SMEM_TOTAL);

    rescal_fused<<<NREL, 128, SMEM_TOTAL>>>(h_idx, r_idx, t_idx, labels,
                                            ent_w, rel_w, out);
}

// round 15
// speedup vs baseline: 1.0249x; 1.0249x over previous
#include <cuda_runtime.h>
#include <cuda_bf16.h>
#include <cstdint>

#define BATCH  16384
#define DIM    128
#define NREL   500
#define MAXC   2048
#define SUBCAP 256
#define ALPHA  0.001f
#define KPB    272       // bytes per bf16 tile row (136 elems)

// device scratch (zero-init at load; self-cleaning across graph replays)
__device__ float g_acc[4];   // 0=sum h^2, 1=sum t^2, 2=sum ||R||^2*count, 3=sum sq err
__device__ int   g_cnt8[NREL * 8];
__device__ int   g_bucket[NREL * MAXC];
__device__ int   g_ready;
__device__ int   g_done;

#define OFF_RLO    (128 * KPB)          // 34816
#define SMEM_TOTAL (2 * 128 * KPB)      // 69632 -> 3 CTAs/SM

extern __shared__ char smem[];

__device__ __forceinline__ uint32_t smem_u32(const void* p) {
    return (uint32_t)__cvta_generic_to_shared(p);
}

__device__ __forceinline__ float warpSum(float v) {
#pragma unroll
    for (int o = 16; o > 0; o >>= 1) v += __shfl_xor_sync(0xffffffffu, v, o);
    return v;
}

__device__ __forceinline__ void split_u32(float x, float y, uint32_t& hi, uint32_t& lo) {
    __nv_bfloat162 h = __floats2bfloat162_rn(x, y);
    __nv_bfloat162 l = __floats2bfloat162_rn(x - __bfloat162float(h.x),
                                             y - __bfloat162float(h.y));
    hi = *reinterpret_cast<uint32_t*>(&h);
    lo = *reinterpret_cast<uint32_t*>(&l);
}

__device__ __forceinline__ void mma_bf16(float& c0, float& c1, float& c2, float& c3,
                                         uint32_t a0, uint32_t a1, uint32_t a2, uint32_t a3,
                                         uint32_t b0, uint32_t b1) {
    asm volatile(
        "mma.sync.aligned.m16n8k16.row.col.f32.bf16.bf16.f32 "
        "{%0,%1,%2,%3}, {%4,%5,%6,%7}, {%8,%9}, {%0,%1,%2,%3};"
        : "+f"(c0), "+f"(c1), "+f"(c2), "+f"(c3)
        : "r"(a0), "r"(a1), "r"(a2), "r"(a3), "r"(b0), "r"(b1));
}

// map logical row r -> global bucket index, via 8-segment prefix in smem
__device__ __forceinline__ int row_lookup(int r, const int* sP, int rel) {
    int sub = 0;
#pragma unroll
    for (int j = 1; j < 8; j++) sub += (r >= sP[j]);
    return g_bucket[rel * MAXC + sub * SUBCAP + (r - sP[sub])];
}

__global__ __launch_bounds__(128, 3) void rescal_fused(
    const int*   __restrict__ h_idx,
    const int*   __restrict__ r_idx,
    const int*   __restrict__ t_idx,
    const float* __restrict__ labels,
    const float* __restrict__ ent_w,
    const float* __restrict__ rel_w,
    float*       __restrict__ out)
{
    __shared__ float sH2, sT2, sE2, sR2;
    __shared__ int   sLast;
    __shared__ int   sP[9];

    const int tid  = threadIdx.x;
    const int lane = tid & 31;
    const int wid  = tid >> 5;
    const int rel  = blockIdx.x;

    char* Rhi = smem;
    char* Rlo = smem + OFF_RLO;

    if (tid == 0) { sH2 = 0.f; sT2 = 0.f; sE2 = 0.f; sR2 = 0.f; sLast = 0; }

    // ---- L2 prefetch of this block's R tile (512 x 128B lines) ----
    const float4* Rg = (const float4*)rel_w + (size_t)rel * 4096;
#pragma unroll
    for (int p = 0; p < 4; p++) {
        const char* a = (const char*)Rg + (tid * 4 + p) * 128;
        asm volatile("prefetch.global.L2 [%0];" :: "l"(a));
    }
    __syncthreads();

    // ---- Phase A: blocks 0..127 bucket 128 indices each; 8 sub-buckets/rel ----
    if (rel < 128) {
        int i   = rel * 128 + tid;
        int rl  = r_idx[i];
        int sub = i & 7;
        int s   = atomicAdd(&g_cnt8[rl * 8 + sub], 1);
        if (s < SUBCAP) g_bucket[rl * MAXC + sub * SUBCAP + s] = i;
        __threadfence();
        __syncthreads();
        if (tid == 0) atomicAdd(&g_ready, 1);
    }

    // ---- Phase B: R [128x128] fp32 -> bf16 hi/lo smem tiles; ||R||^2 ----
    float r2 = 0.f;
#pragma unroll 4
    for (int it = 0; it < 32; it++) {
        int i   = it * 128 + tid;
        int row = i >> 5;
        int col = (i & 31) * 4;
        float4 v = Rg[i];
        r2 += v.x * v.x + v.y * v.y + v.z * v.z + v.w * v.w;
        uint32_t h0, l0, h1, l1;
        split_u32(v.x, v.y, h0, l0);
        split_u32(v.z, v.w, h1, l1);
        *(uint2*)(Rhi + row * KPB + col * 2) = make_uint2(h0, h1);
        *(uint2*)(Rlo + row * KPB + col * 2) = make_uint2(l0, l1);
    }
    r2 = warpSum(r2);
    if (lane == 0) atomicAdd(&sR2, r2);

    // ---- Phase C: wait for bucket producers, then build segment prefix ----
    if (tid == 0) {
        volatile int* p = &g_ready;
        while (*p < 128) { }
        __threadfence();
    }
    __syncthreads();
    if (tid == 0) {
        int acc = 0;
        sP[0] = 0;
#pragma unroll
        for (int j = 0; j < 8; j++) {
            int c = g_cnt8[rel * 8 + j];
            acc += (c < SUBCAP ? c : SUBCAP);
            sP[j + 1] = acc;
        }
    }
    __syncthreads();
    const int count = sP[8];

    float h2 = 0.f, t2 = 0.f, sq = 0.f;
    const int gr  = lane >> 2;   // 0..7
    const int tig = lane & 3;    // 0..3

    // ldmatrix lane base: lanes 0-7 -> hi b0, 8-15 -> hi b1, 16-23 -> lo b0, 24-31 -> lo b1
    const int mm = lane >> 3;    // matrix id 0..3
    const int rr = lane & 7;     // row within matrix (= n within nt-block)
    const uint32_t lane_base =
        (mm < 2 ? smem_u32(Rhi) : smem_u32(Rlo)) + (uint32_t)(rr * KPB + (mm & 1) * 16);

    // ---- Phase D: per-warp 16-row chunks; kt-outer / nt-inner, LDSM B-frags ----
    for (int base = wid * 16; base < count; base += 4 * 16) {
        const int ne   = min(16, count - base);
        const bool ok0 = (gr < ne);
        const bool ok1 = (gr + 8 < ne);

        const int ib0 = ok0 ? row_lookup(base + gr, sP, rel) : 0;
        const int ib1 = ok1 ? row_lookup(base + gr + 8, sP, rel) : 0;
        const float* T0 = ent_w + (size_t)t_idx[ib0] * DIM;
        const float* T1 = ent_w + (size_t)t_idx[ib1] * DIM;
        const float* H0 = ent_w + (size_t)h_idx[ib0] * DIM;
        const float* H1 = ent_w + (size_t)h_idx[ib1] * DIM;

        // preload all A-fragments (T rows gr / gr+8), split to bf16 hi/lo
        uint32_t ah[8][4], al[8][4];
#pragma unroll
        for (int kt = 0; kt < 8; kt++) {
            const int ka = kt * 16 + 2 * tig;
            float2 t0a = ok0 ? *(const float2*)(T0 + ka)     : make_float2(0.f, 0.f);
            float2 t0b = ok0 ? *(const float2*)(T0 + ka + 8) : make_float2(0.f, 0.f);
            float2 t1a = ok1 ? *(const float2*)(T1 + ka)     : make_float2(0.f, 0.f);
            float2 t1b = ok1 ? *(const float2*)(T1 + ka + 8) : make_float2(0.f, 0.f);
            t2 += t0a.x * t0a.x + t0a.y * t0a.y + t0b.x * t0b.x + t0b.y * t0b.y
                + t1a.x * t1a.x + t1a.y * t1a.y + t1b.x * t1b.x + t1b.y * t1b.y;
            split_u32(t0a.x, t0a.y, ah[kt][0], al[kt][0]);
            split_u32(t1a.x, t1a.y, ah[kt][1], al[kt][1]);
            split_u32(t0b.x, t0b.y, ah[kt][2], al[kt][2]);
            split_u32(t1b.x, t1b.y, ah[kt][3], al[kt][3]);
        }

        float s0 = 0.f, s1 = 0.f;

        // two halves of the n-dimension: 8 live accumulator groups each
#pragma unroll
        for (int hh = 0; hh < 2; hh++) {
            float acc[32];
#pragma unroll
            for (int j = 0; j < 32; j++) acc[j] = 0.f;

#pragma unroll
            for (int kt = 0; kt < 8; kt++) {
#pragma unroll
                for (int nt = 0; nt < 8; nt++) {
                    uint32_t addr = lane_base
                                  + (uint32_t)((hh * 8 + nt) * (8 * KPB) + kt * 32);
                    uint32_t bh0, bh1, bl0, bl1;
                    asm volatile(
                        "ldmatrix.sync.aligned.m8n8.x4.shared.b16 {%0,%1,%2,%3}, [%4];"
                        : "=r"(bh0), "=r"(bh1), "=r"(bl0), "=r"(bl1) : "r"(addr));
                    float* c = acc + nt * 4;
                    mma_bf16(c[0], c[1], c[2], c[3],
                             ah[kt][0], ah[kt][1], ah[kt][2], ah[kt][3], bh0, bh1);
                    mma_bf16(c[0], c[1], c[2], c[3],
                             ah[kt][0], ah[kt][1], ah[kt][2], ah[kt][3], bl0, bl1);
                    mma_bf16(c[0], c[1], c[2], c[3],
                             al[kt][0], al[kt][1], al[kt][2], al[kt][3], bh0, bh1);
                }
            }

            // epilogue for this half: score += H . Y
#pragma unroll
            for (int nt = 0; nt < 8; nt++) {
                const int cn = (hh * 8 + nt) * 8 + 2 * tig;
                float2 hA = ok0 ? *(const float2*)(H0 + cn) : make_float2(0.f, 0.f);
                float2 hB = ok1 ? *(const float2*)(H1 + cn) : make_float2(0.f, 0.f);
                h2 += hA.x * hA.x + hA.y * hA.y + hB.x * hB.x + hB.y * hB.y;
                s0 += hA.x * acc[nt * 4 + 0] + hA.y * acc[nt * 4 + 1];
                s1 += hB.x * acc[nt * 4 + 2] + hB.y * acc[nt * 4 + 3];
            }
        }

        s0 += __shfl_xor_sync(0xffffffffu, s0, 1);
        s0 += __shfl_xor_sync(0xffffffffu, s0, 2);
        s1 += __shfl_xor_sync(0xffffffffu, s1, 1);
        s1 += __shfl_xor_sync(0xffffffffu, s1, 2);
        if (tig == 0) {
            if (ok0) {
                out[1 + ib0] = s0;
                float d = s0 - labels[ib0];
                sq += d * d;
            }
            if (ok1) {
                out[1 + ib1] = s1;
                float d = s1 - labels[ib1];
                sq += d * d;
            }
        }
    }

    // ---- Phase E: loss partials + last-block finalize & state reset ----
    h2 = warpSum(h2);
    t2 = warpSum(t2);
    sq = warpSum(sq);
    if (lane == 0) {
        atomicAdd(&sH2, h2);
        atomicAdd(&sT2, t2);
        atomicAdd(&sE2, sq);
    }
    __syncthreads();
    if (tid == 0) {
        atomicAdd(&g_acc[0], sH2);
        atomicAdd(&g_acc[1], sT2);
        atomicAdd(&g_acc[2], sR2 * (float)count);
        atomicAdd(&g_acc[3], sE2);
        __threadfence();
        int old = atomicAdd(&g_done, 1);
        if (old == NREL - 1) sLast = 1;
    }
    __syncthreads();

    if (sLast) {
        for (int i = tid; i < NREL * 8; i += 128) g_cnt8[i] = 0;
        if (tid == 0) {
            __threadfence();
            const float invBD  = 1.0f / ((float)BATCH * (float)DIM);
            const float invBDD = 1.0f / ((float)BATCH * (float)DIM * (float)DIM);
            float norms = (g_acc[0] * invBD + g_acc[1] * invBD + g_acc[2] * invBDD)
                        * (1.0f / 3.0f);
            out[0] = g_acc[3] / (float)BATCH + ALPHA * norms;
            g_acc[0] = 0.f; g_acc[1] = 0.f; g_acc[2] = 0.f; g_acc[3] = 0.f;
            g_done  = 0;
            g_ready = 0;
        }
    }
}

extern "C" void kernel_launch(void* const* d_in, const int* in_sizes, int n_in,
                              void* d_out, int out_size)
{
    const int*   h_idx  = (const int*)d_in[0];
    const int*   r_idx  = (const int*)d_in[1];
    const int*   t_idx  = (const int*)d_in[2];
    const float* labels = (const float*)d_in[3];
    const float* ent_w  = (const float*)d_in[4];
    const float* rel_w  = (const float*)d_in[5];
    float*       out    = (float*)d_out;

    cudaFuncSetAttribute(rescal_fused,
                         cudaFuncAttributeMaxDynamicSharedMemorySize, SMEM_TOTAL);

    rescal_fused<<<NREL, 128, SMEM_TOTAL>>>(h_idx, r_idx, t_idx, labels,
                                            ent_w, rel_w, out);
}

// round 16
// speedup vs baseline: 1.1026x; 1.0758x over previous
#include <cuda_runtime.h>
#include <cuda_bf16.h>
#include <cstdint>

#define BATCH  16384
#define DIM    128
#define NREL   500
#define MAXC   2048
#define SUBCAP 256
#define ALPHA  0.001f
#define KPB    272       // bytes per bf16 tile row (136 elems -> conflict-free LDS.32)

// device scratch (zero-init at load; self-cleaning across graph replays)
__device__ float g_acc[4];   // 0=sum h^2, 1=sum t^2, 2=sum ||R||^2*count, 3=sum sq err
__device__ int   g_cnt8[NREL * 8];
__device__ int   g_bucket[NREL * MAXC];
__device__ int   g_ready;
__device__ int   g_done;

#define OFF_RLO    (128 * KPB)          // 34816
#define SMEM_TOTAL (2 * 128 * KPB)      // 69632 -> 3 CTAs/SM

extern __shared__ char smem[];

__device__ __forceinline__ float warpSum(float v) {
#pragma unroll
    for (int o = 16; o > 0; o >>= 1) v += __shfl_xor_sync(0xffffffffu, v, o);
    return v;
}

__device__ __forceinline__ void split_u32(float x, float y, uint32_t& hi, uint32_t& lo) {
    __nv_bfloat162 h = __floats2bfloat162_rn(x, y);
    __nv_bfloat162 l = __floats2bfloat162_rn(x - __bfloat162float(h.x),
                                             y - __bfloat162float(h.y));
    hi = *reinterpret_cast<uint32_t*>(&h);
    lo = *reinterpret_cast<uint32_t*>(&l);
}

__device__ __forceinline__ void mma_bf16(float& c0, float& c1, float& c2, float& c3,
                                         uint32_t a0, uint32_t a1, uint32_t a2, uint32_t a3,
                                         uint32_t b0, uint32_t b1) {
    asm volatile(
        "mma.sync.aligned.m16n8k16.row.col.f32.bf16.bf16.f32 "
        "{%0,%1,%2,%3}, {%4,%5,%6,%7}, {%8,%9}, {%0,%1,%2,%3};"
        : "+f"(c0), "+f"(c1), "+f"(c2), "+f"(c3)
        : "r"(a0), "r"(a1), "r"(a2), "r"(a3), "r"(b0), "r"(b1));
}

// map logical row r -> global bucket index, via 8-segment prefix in smem
__device__ __forceinline__ int row_lookup(int r, const int* sP, int rel) {
    int sub = 0;
#pragma unroll
    for (int j = 1; j < 8; j++) sub += (r >= sP[j]);
    return g_bucket[rel * MAXC + sub * SUBCAP + (r - sP[sub])];
}

__global__ __launch_bounds__(128, 3) void rescal_fused(
    const int*   __restrict__ h_idx,
    const int*   __restrict__ r_idx,
    const int*   __restrict__ t_idx,
    const float* __restrict__ labels,
    const float* __restrict__ ent_w,
    const float* __restrict__ rel_w,
    float*       __restrict__ out)
{
    __shared__ float sH2, sT2, sE2, sR2;
    __shared__ int   sLast;
    __shared__ int   sP[9];

    const int tid  = threadIdx.x;
    const int lane = tid & 31;
    const int wid  = tid >> 5;
    const int rel  = blockIdx.x;

    char* Rhi = smem;
    char* Rlo = smem + OFF_RLO;

    if (tid == 0) { sH2 = 0.f; sT2 = 0.f; sE2 = 0.f; sR2 = 0.f; sLast = 0; }
    __syncthreads();

    // ---- Phase A: blocks 0..127 bucket 128 indices each; 8 sub-buckets/rel ----
    if (rel < 128) {
        int i   = rel * 128 + tid;
        int rl  = r_idx[i];
        int sub = i & 7;
        int s   = atomicAdd(&g_cnt8[rl * 8 + sub], 1);
        if (s < SUBCAP) g_bucket[rl * MAXC + sub * SUBCAP + s] = i;
        __threadfence();
        __syncthreads();
        if (tid == 0) atomicAdd(&g_ready, 1);
    }

    // ---- Phase B: R [128x128] fp32 -> bf16 hi/lo smem tiles; ||R||^2 ----
    const float4* Rg = (const float4*)rel_w + (size_t)rel * 4096;
    float r2 = 0.f;
#pragma unroll 4
    for (int it = 0; it < 32; it++) {
        int i   = it * 128 + tid;
        int row = i >> 5;
        int col = (i & 31) * 4;
        float4 v = Rg[i];
        r2 += v.x * v.x + v.y * v.y + v.z * v.z + v.w * v.w;
        uint32_t h0, l0, h1, l1;
        split_u32(v.x, v.y, h0, l0);
        split_u32(v.z, v.w, h1, l1);
        *(uint2*)(Rhi + row * KPB + col * 2) = make_uint2(h0, h1);
        *(uint2*)(Rlo + row * KPB + col * 2) = make_uint2(l0, l1);
    }
    r2 = warpSum(r2);
    if (lane == 0) atomicAdd(&sR2, r2);

    // ---- Phase C: wait for bucket producers, then build segment prefix ----
    if (tid == 0) {
        volatile int* p = &g_ready;
        while (*p < 128) { }
        __threadfence();
    }
    __syncthreads();
    if (tid == 0) {
        int acc = 0;
        sP[0] = 0;
#pragma unroll
        for (int j = 0; j < 8; j++) {
            int c = g_cnt8[rel * 8 + j];
            acc += (c < SUBCAP ? c : SUBCAP);
            sP[j + 1] = acc;
        }
    }
    __syncthreads();
    const int count = sP[8];

    float h2 = 0.f, t2 = 0.f, sq = 0.f;
    const int gr  = lane >> 2;   // 0..7
    const int tig = lane & 3;    // 0..3

    // even-split chunking: all 4 warps get work (count=33 -> 9/9/9/6)
    const int per = min(16, (count + 3) >> 2);

    // ---- Phase D: per-warp chunks of `per` rows; kt-outer / nt-inner MMA ----
    for (int base = wid * per; base < count; base += 4 * per) {
        const int ne   = min(per, count - base);
        const bool ok0 = (gr < ne);
        const bool ok1 = (gr + 8 < ne);

        const int ib0 = ok0 ? row_lookup(base + gr, sP, rel) : 0;
        const int ib1 = ok1 ? row_lookup(base + gr + 8, sP, rel) : 0;
        const float* T0 = ent_w + (size_t)t_idx[ib0] * DIM;
        const float* T1 = ent_w + (size_t)t_idx[ib1] * DIM;
        const float* H0 = ent_w + (size_t)h_idx[ib0] * DIM;
        const float* H1 = ent_w + (size_t)h_idx[ib1] * DIM;

        // preload all A-fragments (T rows gr / gr+8), split to bf16 hi/lo
        uint32_t ah[8][4], al[8][4];
#pragma unroll
        for (int kt = 0; kt < 8; kt++) {
            const int ka = kt * 16 + 2 * tig;
            float2 t0a = ok0 ? *(const float2*)(T0 + ka)     : make_float2(0.f, 0.f);
            float2 t0b = ok0 ? *(const float2*)(T0 + ka + 8) : make_float2(0.f, 0.f);
            float2 t1a = ok1 ? *(const float2*)(T1 + ka)     : make_float2(0.f, 0.f);
            float2 t1b = ok1 ? *(const float2*)(T1 + ka + 8) : make_float2(0.f, 0.f);
            t2 += t0a.x * t0a.x + t0a.y * t0a.y + t0b.x * t0b.x + t0b.y * t0b.y
                + t1a.x * t1a.x + t1a.y * t1a.y + t1b.x * t1b.x + t1b.y * t1b.y;
            split_u32(t0a.x, t0a.y, ah[kt][0], al[kt][0]);
            split_u32(t1a.x, t1a.y, ah[kt][1], al[kt][1]);
            split_u32(t0b.x, t0b.y, ah[kt][2], al[kt][2]);
            split_u32(t1b.x, t1b.y, ah[kt][3], al[kt][3]);
        }

        float s0 = 0.f, s1 = 0.f;

        // two halves of the n-dimension: 8 live accumulator groups each
#pragma unroll
        for (int hh = 0; hh < 2; hh++) {
            float acc[32];
#pragma unroll
            for (int j = 0; j < 32; j++) acc[j] = 0.f;

#pragma unroll
            for (int kt = 0; kt < 8; kt++) {
                const int kb = kt * 32 + 4 * tig;
#pragma unroll
                for (int nt = 0; nt < 8; nt++) {
                    const int n = (hh * 8 + nt) * 8 + gr;
                    const char* rh = Rhi + n * KPB;
                    const char* rl = Rlo + n * KPB;
                    uint32_t bh0 = *(const uint32_t*)(rh + kb);
                    uint32_t bh1 = *(const uint32_t*)(rh + kb + 16);
                    uint32_t bl0 = *(const uint32_t*)(rl + kb);
                    uint32_t bl1 = *(const uint32_t*)(rl + kb + 16);
                    float* c = acc + nt * 4;
                    mma_bf16(c[0], c[1], c[2], c[3],
                             ah[kt][0], ah[kt][1], ah[kt][2], ah[kt][3], bh0, bh1);
                    mma_bf16(c[0], c[1], c[2], c[3],
                             ah[kt][0], ah[kt][1], ah[kt][2], ah[kt][3], bl0, bl1);
                    mma_bf16(c[0], c[1], c[2], c[3],
                             al[kt][0], al[kt][1], al[kt][2], al[kt][3], bh0, bh1);
                }
            }

            // epilogue for this half: score += H . Y
#pragma unroll
            for (int nt = 0; nt < 8; nt++) {
                const int cn = (hh * 8 + nt) * 8 + 2 * tig;
                float2 hA = ok0 ? *(const float2*)(H0 + cn) : make_float2(0.f, 0.f);
                float2 hB = ok1 ? *(const float2*)(H1 + cn) : make_float2(0.f, 0.f);
                h2 += hA.x * hA.x + hA.y * hA.y + hB.x * hB.x + hB.y * hB.y;
                s0 += hA.x * acc[nt * 4 + 0] + hA.y * acc[nt * 4 + 1];
                s1 += hB.x * acc[nt * 4 + 2] + hB.y * acc[nt * 4 + 3];
            }
        }

        s0 += __shfl_xor_sync(0xffffffffu, s0, 1);
        s0 += __shfl_xor_sync(0xffffffffu, s0, 2);
        s1 += __shfl_xor_sync(0xffffffffu, s1, 1);
        s1 += __shfl_xor_sync(0xffffffffu, s1, 2);
        if (tig == 0) {
            if (ok0) {
                out[1 + ib0] = s0;
                float d = s0 - labels[ib0];
                sq += d * d;
            }
            if (ok1) {
                out[1 + ib1] = s1;
                float d = s1 - labels[ib1];
                sq += d * d;
            }
        }
    }

    // ---- Phase E: loss partials + last-block finalize & state reset ----
    h2 = warpSum(h2);
    t2 = warpSum(t2);
    sq = warpSum(sq);
    if (lane == 0) {
        atomicAdd(&sH2, h2);
        atomicAdd(&sT2, t2);
        atomicAdd(&sE2, sq);
    }
    __syncthreads();
    if (tid == 0) {
        atomicAdd(&g_acc[0], sH2);
        atomicAdd(&g_acc[1], sT2);
        atomicAdd(&g_acc[2], sR2 * (float)count);
        atomicAdd(&g_acc[3], sE2);
        __threadfence();
        int old = atomicAdd(&g_done, 1);
        if (old == NREL - 1) sLast = 1;
    }
    __syncthreads();

    if (sLast) {
        for (int i = tid; i < NREL * 8; i += 128) g_cnt8[i] = 0;
        if (tid == 0) {
            __threadfence();
            const float invBD  = 1.0f / ((float)BATCH * (float)DIM);
            const float invBDD = 1.0f / ((float)BATCH * (float)DIM * (float)DIM);
            float norms = (g_acc[0] * invBD + g_acc[1] * invBD + g_acc[2] * invBDD)
                        * (1.0f / 3.0f);
            out[0] = g_acc[3] / (float)BATCH + ALPHA * norms;
            g_acc[0] = 0.f; g_acc[1] = 0.f; g_acc[2] = 0.f; g_acc[3] = 0.f;
            g_done  = 0;
            g_ready = 0;
        }
    }
}

extern "C" void kernel_launch(void* const* d_in, const int* in_sizes, int n_in,
                              void* d_out, int out_size)
{
    const int*   h_idx  = (const int*)d_in[0];
    const int*   r_idx  = (const int*)d_in[1];
    const int*   t_idx  = (const int*)d_in[2];
    const float* labels = (const float*)d_in[3];
    const float* ent_w  = (const float*)d_in[4];
    const float* rel_w  = (const float*)d_in[5];
    float*       out    = (float*)d_out;

    cudaFuncSetAttribute(rescal_fused,
                         cudaFuncAttributeMaxDynamicSharedMemorySize, SMEM_TOTAL);

    rescal_fused<<<NREL, 128, SMEM_TOTAL>>>(h_idx, r_idx, t_idx, labels,
                                            ent_w, rel_w, out);
}

// round 17
// speedup vs baseline: 1.1063x; 1.0034x over previous
#include <cuda_runtime.h>
#include <cuda_bf16.h>
#include <cstdint>

#define BATCH  16384
#define DIM    128
#define NREL   500
#define MAXC   2048
#define SUBCAP 256
#define ALPHA  0.001f
#define KPB    272       // bytes per bf16 tile row (136 elems -> conflict-free LDS.32)
#define NBLK   444       // 3 CTAs/SM * 148 SMs = exactly one wave

// device scratch (zero-init at load; self-cleaning across graph replays)
__device__ float g_acc[4];   // 0=sum h^2, 1=sum t^2, 2=sum ||R||^2*count, 3=sum sq err
__device__ int   g_cnt8[NREL * 8];
__device__ int   g_bucket[NREL * MAXC];
__device__ int   g_ready;
__device__ int   g_done;
__device__ int   g_next;     // work-steal counter for rels 444..499

#define OFF_RLO    (128 * KPB)          // 34816
#define SMEM_TOTAL (2 * 128 * KPB)      // 69632 -> 3 CTAs/SM

extern __shared__ char smem[];

__device__ __forceinline__ float warpSum(float v) {
#pragma unroll
    for (int o = 16; o > 0; o >>= 1) v += __shfl_xor_sync(0xffffffffu, v, o);
    return v;
}

__device__ __forceinline__ void split_u32(float x, float y, uint32_t& hi, uint32_t& lo) {
    __nv_bfloat162 h = __floats2bfloat162_rn(x, y);
    __nv_bfloat162 l = __floats2bfloat162_rn(x - __bfloat162float(h.x),
                                             y - __bfloat162float(h.y));
    hi = *reinterpret_cast<uint32_t*>(&h);
    lo = *reinterpret_cast<uint32_t*>(&l);
}

__device__ __forceinline__ void mma_bf16(float& c0, float& c1, float& c2, float& c3,
                                         uint32_t a0, uint32_t a1, uint32_t a2, uint32_t a3,
                                         uint32_t b0, uint32_t b1) {
    asm volatile(
        "mma.sync.aligned.m16n8k16.row.col.f32.bf16.bf16.f32 "
        "{%0,%1,%2,%3}, {%4,%5,%6,%7}, {%8,%9}, {%0,%1,%2,%3};"
        : "+f"(c0), "+f"(c1), "+f"(c2), "+f"(c3)
        : "r"(a0), "r"(a1), "r"(a2), "r"(a3), "r"(b0), "r"(b1));
}

// map logical row r -> global bucket index, via 8-segment prefix in smem
__device__ __forceinline__ int row_lookup(int r, const int* sP, int rel) {
    int sub = 0;
#pragma unroll
    for (int j = 1; j < 8; j++) sub += (r >= sP[j]);
    return g_bucket[rel * MAXC + sub * SUBCAP + (r - sP[sub])];
}

__global__ __launch_bounds__(128, 3) void rescal_fused(
    const int*   __restrict__ h_idx,
    const int*   __restrict__ r_idx,
    const int*   __restrict__ t_idx,
    const float* __restrict__ labels,
    const float* __restrict__ ent_w,
    const float* __restrict__ rel_w,
    float*       __restrict__ out)
{
    __shared__ float sH2, sT2, sE2, sR2, sR2C;
    __shared__ int   sLast, sNext;
    __shared__ int   sP[9];

    const int tid  = threadIdx.x;
    const int lane = tid & 31;
    const int wid  = tid >> 5;
    const int bid  = blockIdx.x;

    char* Rhi = smem;
    char* Rlo = smem + OFF_RLO;

    if (tid == 0) { sH2 = 0.f; sT2 = 0.f; sE2 = 0.f; sR2C = 0.f; sLast = 0; }

    // ---- Phase A: blocks 0..127 bucket 128 indices each; 8 sub-buckets/rel ----
    if (bid < 128) {
        int i   = bid * 128 + tid;
        int rl  = r_idx[i];
        int sub = i & 7;
        int s   = atomicAdd(&g_cnt8[rl * 8 + sub], 1);
        if (s < SUBCAP) g_bucket[rl * MAXC + sub * SUBCAP + s] = i;
        __threadfence();
        __syncthreads();
        if (tid == 0) atomicAdd(&g_ready, 1);
    }

    float h2 = 0.f, t2 = 0.f, sq = 0.f;
    const int gr  = lane >> 2;   // 0..7
    const int tig = lane & 3;    // 0..3

    int rel = bid;               // first assignment: one rel per block

    for (;;) {
        if (tid == 0) sR2 = 0.f;
        __syncthreads();   // previous Phase D complete -> safe to overwrite tiles

        // ---- Phase B: R [128x128] fp32 -> bf16 hi/lo smem tiles; ||R||^2 ----
        const float4* Rg = (const float4*)rel_w + (size_t)rel * 4096;
        float r2 = 0.f;
#pragma unroll 4
        for (int it = 0; it < 32; it++) {
            int i   = it * 128 + tid;
            int row = i >> 5;
            int col = (i & 31) * 4;
            float4 v = Rg[i];
            r2 += v.x * v.x + v.y * v.y + v.z * v.z + v.w * v.w;
            uint32_t u0, l0, u1, l1;
            split_u32(v.x, v.y, u0, l0);
            split_u32(v.z, v.w, u1, l1);
            *(uint2*)(Rhi + row * KPB + col * 2) = make_uint2(u0, u1);
            *(uint2*)(Rlo + row * KPB + col * 2) = make_uint2(l0, l1);
        }
        r2 = warpSum(r2);
        if (lane == 0) atomicAdd(&sR2, r2);

        // ---- Phase C: wait for bucket producers (fast after first pass) ----
        if (tid == 0) {
            volatile int* p = &g_ready;
            while (*p < 128) { }
            __threadfence();
        }
        __syncthreads();
        if (tid == 0) {
            int acc = 0;
            sP[0] = 0;
#pragma unroll
            for (int j = 0; j < 8; j++) {
                int c = g_cnt8[rel * 8 + j];
                acc += (c < SUBCAP ? c : SUBCAP);
                sP[j + 1] = acc;
            }
            sR2C += sR2 * (float)acc;   // per-rel ||R||^2 * count, block-accumulated
        }
        __syncthreads();
        const int count = sP[8];

        // even-split chunking: all 4 warps get work (count=33 -> 9/9/9/6)
        const int per = min(16, (count + 3) >> 2);

        // ---- Phase D: per-warp chunks of `per` rows; kt-outer / nt-inner MMA ----
        for (int base = wid * per; base < count; base += 4 * per) {
            const int ne   = min(per, count - base);
            const bool ok0 = (gr < ne);
            const bool ok1 = (gr + 8 < ne);

            const int ib0 = ok0 ? row_lookup(base + gr, sP, rel) : 0;
            const int ib1 = ok1 ? row_lookup(base + gr + 8, sP, rel) : 0;
            const float* T0 = ent_w + (size_t)t_idx[ib0] * DIM;
            const float* T1 = ent_w + (size_t)t_idx[ib1] * DIM;
            const float* H0 = ent_w + (size_t)h_idx[ib0] * DIM;
            const float* H1 = ent_w + (size_t)h_idx[ib1] * DIM;

            // preload all A-fragments (T rows gr / gr+8), split to bf16 hi/lo
            uint32_t ah[8][4], al[8][4];
#pragma unroll
            for (int kt = 0; kt < 8; kt++) {
                const int ka = kt * 16 + 2 * tig;
                float2 t0a = ok0 ? *(const float2*)(T0 + ka)     : make_float2(0.f, 0.f);
                float2 t0b = ok0 ? *(const float2*)(T0 + ka + 8) : make_float2(0.f, 0.f);
                float2 t1a = ok1 ? *(const float2*)(T1 + ka)     : make_float2(0.f, 0.f);
                float2 t1b = ok1 ? *(const float2*)(T1 + ka + 8) : make_float2(0.f, 0.f);
                t2 += t0a.x * t0a.x + t0a.y * t0a.y + t0b.x * t0b.x + t0b.y * t0b.y
                    + t1a.x * t1a.x + t1a.y * t1a.y + t1b.x * t1b.x + t1b.y * t1b.y;
                split_u32(t0a.x, t0a.y, ah[kt][0], al[kt][0]);
                split_u32(t1a.x, t1a.y, ah[kt][1], al[kt][1]);
                split_u32(t0b.x, t0b.y, ah[kt][2], al[kt][2]);
                split_u32(t1b.x, t1b.y, ah[kt][3], al[kt][3]);
            }

            float s0 = 0.f, s1 = 0.f;

            // two halves of the n-dimension: 8 live accumulator groups each
#pragma unroll
            for (int hh = 0; hh < 2; hh++) {
                float acc[32];
#pragma unroll
                for (int j = 0; j < 32; j++) acc[j] = 0.f;

#pragma unroll
                for (int kt = 0; kt < 8; kt++) {
                    const int kb = kt * 32 + 4 * tig;
#pragma unroll
                    for (int nt = 0; nt < 8; nt++) {
                        const int n = (hh * 8 + nt) * 8 + gr;
                        const char* rh = Rhi + n * KPB;
                        const char* rl = Rlo + n * KPB;
                        uint32_t bh0 = *(const uint32_t*)(rh + kb);
                        uint32_t bh1 = *(const uint32_t*)(rh + kb + 16);
                        uint32_t bl0 = *(const uint32_t*)(rl + kb);
                        uint32_t bl1 = *(const uint32_t*)(rl + kb + 16);
                        float* c = acc + nt * 4;
                        mma_bf16(c[0], c[1], c[2], c[3],
                                 ah[kt][0], ah[kt][1], ah[kt][2], ah[kt][3], bh0, bh1);
                        mma_bf16(c[0], c[1], c[2], c[3],
                                 ah[kt][0], ah[kt][1], ah[kt][2], ah[kt][3], bl0, bl1);
                        mma_bf16(c[0], c[1], c[2], c[3],
                                 al[kt][0], al[kt][1], al[kt][2], al[kt][3], bh0, bh1);
                    }
                }

                // epilogue for this half: score += H . Y
#pragma unroll
                for (int nt = 0; nt < 8; nt++) {
                    const int cn = (hh * 8 + nt) * 8 + 2 * tig;
                    float2 hA = ok0 ? *(const float2*)(H0 + cn) : make_float2(0.f, 0.f);
                    float2 hB = ok1 ? *(const float2*)(H1 + cn) : make_float2(0.f, 0.f);
                    h2 += hA.x * hA.x + hA.y * hA.y + hB.x * hB.x + hB.y * hB.y;
                    s0 += hA.x * acc[nt * 4 + 0] + hA.y * acc[nt * 4 + 1];
                    s1 += hB.x * acc[nt * 4 + 2] + hB.y * acc[nt * 4 + 3];
                }
            }

            s0 += __shfl_xor_sync(0xffffffffu, s0, 1);
            s0 += __shfl_xor_sync(0xffffffffu, s0, 2);
            s1 += __shfl_xor_sync(0xffffffffu, s1, 1);
            s1 += __shfl_xor_sync(0xffffffffu, s1, 2);
            if (tig == 0) {
                if (ok0) {
                    out[1 + ib0] = s0;
                    float d = s0 - labels[ib0];
                    sq += d * d;
                }
                if (ok1) {
                    out[1 + ib1] = s1;
                    float d = s1 - labels[ib1];
                    sq += d * d;
                }
            }
        }

        // ---- steal next relation ----
        if (tid == 0) sNext = NBLK + atomicAdd(&g_next, 1);
        __syncthreads();
        rel = sNext;
        if (rel >= NREL) break;
    }

    // ---- Phase E: loss partials + last-block finalize & state reset ----
    h2 = warpSum(h2);
    t2 = warpSum(t2);
    sq = warpSum(sq);
    if (lane == 0) {
        atomicAdd(&sH2, h2);
        atomicAdd(&sT2, t2);
        atomicAdd(&sE2, sq);
    }
    __syncthreads();
    if (tid == 0) {
        atomicAdd(&g_acc[0], sH2);
        atomicAdd(&g_acc[1], sT2);
        atomicAdd(&g_acc[2], sR2C);
        atomicAdd(&g_acc[3], sE2);
        __threadfence();
        int old = atomicAdd(&g_done, 1);
        if (old == NBLK - 1) sLast = 1;
    }
    __syncthreads();

    if (sLast) {
        for (int i = tid; i < NREL * 8; i += 128) g_cnt8[i] = 0;
        if (tid == 0) {
            __threadfence();
            const float invBD  = 1.0f / ((float)BATCH * (float)DIM);
            const float invBDD = 1.0f / ((float)BATCH * (float)DIM * (float)DIM);
            float norms = (g_acc[0] * invBD + g_acc[1] * invBD + g_acc[2] * invBDD)
                        * (1.0f / 3.0f);
            out[0] = g_acc[3] / (float)BATCH + ALPHA * norms;
            g_acc[0] = 0.f; g_acc[1] = 0.f; g_acc[2] = 0.f; g_acc[3] = 0.f;
            g_done  = 0;
            g_ready = 0;
            g_next  = 0;
        }
    }
}

extern "C" void kernel_launch(void* const* d_in, const int* in_sizes, int n_in,
                              void* d_out, int out_size)
{
    const int*   h_idx  = (const int*)d_in[0];
    const int*   r_idx  = (const int*)d_in[1];
    const int*   t_idx  = (const int*)d_in[2];
    const float* labels = (const float*)d_in[3];
    const float* ent_w  = (const float*)d_in[4];
    const float* rel_w  = (const float*)d_in[5];
    float*       out    = (float*)d_out;

    cudaFuncSetAttribute(rescal_fused,
                         cudaFuncAttributeMaxDynamicSharedMemorySize, SMEM_TOTAL);

    rescal_fused<<<NBLK, 128, SMEM_TOTAL>>>(h_idx, r_idx, t_idx, labels,
                                            ent_w, rel_w, out);
}